// round 9
// baseline (speedup 1.0000x reference)
#include <cuda_runtime.h>
#include <cuda_bf16.h>
#include <cstdint>
#include <math.h>

// Problem constants (B=8, H=W=128, C=384, window=8)
#define TOKENS   131072              // 8*128*128
#define CDIM     384
#define NQKV     1152
#define NWIN     2048                // 8 * 16 * 16 windows

// ---------------------------------------------------------------------------
// Scratch (allocation-free rule: __device__ globals)
// ---------------------------------------------------------------------------
__device__ float g_qkv[(size_t)TOKENS * NQKV];   // fp32 qkv (604 MB)
__device__ float g_att[(size_t)TOKENS * CDIM];   // fp32 attention out (201 MB)
__device__ float g_Wt1[(size_t)NQKV * CDIM];     // w_qkv^T  [N][K], tf32-rounded
__device__ float g_Wt3[(size_t)CDIM * CDIM];     // w_proj^T [N][K], tf32-rounded

__device__ __forceinline__ uint32_t smem_u32(const void* p) {
    uint32_t a;
    asm("{ .reg .u64 tmp; cvta.to.shared.u64 tmp, %1; cvt.u32.u64 %0, tmp; }"
        : "=r"(a) : "l"(p));
    return a;
}

// Split a float2 into packed bf16x2 hi and lo (residual) parts.
__device__ __forceinline__ void split2(float x, float y, uint32_t& hi, uint32_t& lo) {
    uint32_t h;
    asm("cvt.rn.bf16x2.f32 %0, %1, %2;" : "=r"(h) : "f"(y), "f"(x));
    float h0 = __uint_as_float(h << 16);
    float h1 = __uint_as_float(h & 0xffff0000u);
    float r0 = x - h0, r1 = y - h1;
    asm("cvt.rn.bf16x2.f32 %0, %1, %2;" : "=r"(lo) : "f"(r1), "f"(r0));
    hi = h;
}

__device__ __forceinline__ void mma_tf32(float* c, const uint32_t* a,
                                         uint32_t b0, uint32_t b1) {
    asm volatile(
        "mma.sync.aligned.m16n8k8.row.col.f32.tf32.tf32.f32 "
        "{%0,%1,%2,%3}, {%4,%5,%6,%7}, {%8,%9}, {%0,%1,%2,%3};\n"
        : "+f"(c[0]), "+f"(c[1]), "+f"(c[2]), "+f"(c[3])
        : "r"(a[0]), "r"(a[1]), "r"(a[2]), "r"(a[3]), "r"(b0), "r"(b1));
}

__device__ __forceinline__ void mma16816(float* c, const uint32_t* a,
                                         uint32_t b0, uint32_t b1) {
    asm volatile(
        "mma.sync.aligned.m16n8k16.row.col.f32.bf16.bf16.f32 "
        "{%0,%1,%2,%3}, {%4,%5,%6,%7}, {%8,%9}, {%0,%1,%2,%3};\n"
        : "+f"(c[0]), "+f"(c[1]), "+f"(c[2]), "+f"(c[3])
        : "r"(a[0]), "r"(a[1]), "r"(a[2]), "r"(a[3]), "r"(b0), "r"(b1));
}

#define LDSM_X4(r, a) \
    asm volatile("ldmatrix.sync.aligned.m8n8.x4.shared.b16 {%0,%1,%2,%3}, [%4];" \
        : "=r"((r)[0]), "=r"((r)[1]), "=r"((r)[2]), "=r"((r)[3]) : "r"(a))

#define LDSM_X4_T(r, a) \
    asm volatile("ldmatrix.sync.aligned.m8n8.x4.trans.shared.b16 {%0,%1,%2,%3}, [%4];" \
        : "=r"((r)[0]), "=r"((r)[1]), "=r"((r)[2]), "=r"((r)[3]) : "r"(a))

#define CVT_TF32(r) \
    asm("cvt.rna.tf32.f32 %0, %0;" : "+r"(r))

// ---------------------------------------------------------------------------
// Weight transpose + tf32 rounding: w [384 x N] fp32 -> out [N x 384]
// ---------------------------------------------------------------------------
__global__ __launch_bounds__(256) void trans_w_kernel(
    const float* __restrict__ w, float* __restrict__ out, int N)
{
    const int t = blockIdx.x * 256 + threadIdx.x;
    if (t >= N * CDIM) return;
    const int n = t / CDIM;
    const int k = t % CDIM;
    uint32_t v = __float_as_uint(w[(size_t)k * N + n]);
    CVT_TF32(v);
    out[(size_t)n * CDIM + k] = __uint_as_float(v);
}

// ---------------------------------------------------------------------------
// TF32 GEMM (unchanged from round 8 — validated at 1181 us total)
// ---------------------------------------------------------------------------
#define STAGE_BYTES 32768u
__global__ __launch_bounds__(256, 2) void gemm_tf32(
    const float* __restrict__ A,
    const float* __restrict__ Bt,
    const float* __restrict__ bias,
    float* __restrict__ C, int Ndim)
{
    extern __shared__ __align__(16) char smem[];
    const uint32_t smemBase = smem_u32(smem);

    const int tid  = threadIdx.x;
    const int wid  = tid >> 5;
    const int lane = tid & 31;
    const int g    = lane >> 2;
    const int t4   = lane & 3;
    const int m0   = blockIdx.y * 128;
    const int n0   = blockIdx.x * 128;
    const int wm   = (wid & 3) * 32;
    const int wn   = (wid >> 2) * 64;

    const float* srcs[8];
    uint32_t dsts[8];
#pragma unroll
    for (int i = 0; i < 8; i++) {
        const int id = tid + i * 256;
        const int ab = id >> 10;
        const int r  = (id >> 3) & 127;
        const int ch = id & 7;
        if (ab == 0) srcs[i] = A  + (size_t)(m0 + r) * CDIM + ch * 4;
        else         srcs[i] = Bt + (size_t)(n0 + r) * CDIM + ch * 4;
        dsts[i] = smemBase + (uint32_t)(ab * 16384 + r * 128 + (ch ^ (r & 7)) * 16);
    }

#define PREFETCH(s, off) do {                                                 \
        _Pragma("unroll")                                                     \
        for (int _i = 0; _i < 8; _i++) {                                      \
            asm volatile("cp.async.cg.shared.global [%0], [%1], 16;"          \
                :: "r"(dsts[_i] + (off)), "l"(srcs[_i] + (s) * 32));          \
        }                                                                     \
        asm volatile("cp.async.commit_group;" ::: "memory");                  \
    } while (0)

    const int la = lane & 15;
    const int h  = lane >> 4;
    const int s7 = la & 7;
    uint32_t coff[4];
#pragma unroll
    for (int q = 0; q < 4; q++)
        coff[q] = (uint32_t)((((2 * q + h) ^ s7) & 7) * 16);
    const uint32_t aBase = smemBase + (uint32_t)((wm + la) * 128);
    const uint32_t bBase = smemBase + 16384 + (uint32_t)((wn + la) * 128);

    float acc[2][8][4];
#pragma unroll
    for (int mt = 0; mt < 2; mt++)
#pragma unroll
        for (int nt = 0; nt < 8; nt++)
#pragma unroll
            for (int i = 0; i < 4; i++) acc[mt][nt][i] = 0.f;

    PREFETCH(0, 0);
    PREFETCH(1, STAGE_BYTES);

#pragma unroll
    for (int s = 0; s < 12; s++) {
        asm volatile("cp.async.wait_group 1;" ::: "memory");
        __syncthreads();
        if (s < 10) PREFETCH(s + 2, ((s + 2) % 3) * STAGE_BYTES);
        else asm volatile("cp.async.commit_group;" ::: "memory");
        const uint32_t off = (s % 3) * STAGE_BYTES;

#pragma unroll
        for (int q = 0; q < 4; q++) {
            uint32_t a[2][4];
#pragma unroll
            for (int mt = 0; mt < 2; mt++) {
                LDSM_X4(a[mt], aBase + off + mt * 2048 + coff[q]);
                CVT_TF32(a[mt][0]); CVT_TF32(a[mt][1]);
                CVT_TF32(a[mt][2]); CVT_TF32(a[mt][3]);
            }
#pragma unroll
            for (int ntp = 0; ntp < 4; ntp++) {
                uint32_t b[4];
                LDSM_X4(b, bBase + off + ntp * 2048 + coff[q]);
                mma_tf32(acc[0][ntp * 2],     a[0], b[0], b[2]);
                mma_tf32(acc[0][ntp * 2 + 1], a[0], b[1], b[3]);
                mma_tf32(acc[1][ntp * 2],     a[1], b[0], b[2]);
                mma_tf32(acc[1][ntp * 2 + 1], a[1], b[1], b[3]);
            }
        }
    }
#undef PREFETCH

#pragma unroll
    for (int mt = 0; mt < 2; mt++) {
        const int r0 = m0 + wm + mt * 16 + g;
#pragma unroll
        for (int nt = 0; nt < 8; nt++) {
            const int col = n0 + wn + (nt >> 1) * 16 + (nt & 1) * 8 + t4 * 2;
            float2 bv = *(const float2*)(bias + col);
            float2 v0 = make_float2(acc[mt][nt][0] + bv.x, acc[mt][nt][1] + bv.y);
            float2 v1 = make_float2(acc[mt][nt][2] + bv.x, acc[mt][nt][3] + bv.y);
            *(float2*)(C + (size_t)r0 * Ndim + col) = v0;
            *(float2*)(C + (size_t)(r0 + 8) * Ndim + col) = v1;
        }
    }
}

// ---------------------------------------------------------------------------
// Window attention v2: split-bf16 HMMA for S=QK^T and O=PV, fp32 softmax.
//   1 window / block, 128 threads (4 warps, 16 q-rows each).
//   smem: [0,32K) QK hi/lo planes (Ss fp32 [64][65] overlays after S;
//         V hi/lo planes overlay during O), [32K,48K) P hi/lo, [48K) tok.
// ---------------------------------------------------------------------------
#define ATTN_SMEM 49408
__global__ __launch_bounds__(128) void window_attn()
{
    extern __shared__ __align__(16) char asm_[];
    const uint32_t sb = smem_u32(asm_);
    int* tok = (int*)(asm_ + 49152);
    float (*Ss)[65] = (float(*)[65])asm_;

    const int gb = blockIdx.x;
    const int b = gb >> 8, win = gb & 255, wy = win >> 4, wx = win & 15;
    const int tid = threadIdx.x;
    if (tid < 64) {
        int py = tid >> 3, px = tid & 7;
        tok[tid] = b * 16384 + (wy * 8 + py) * 128 + (wx * 8 + px);
    }
    __syncthreads();

    const int wid = tid >> 5, lane = tid & 31;
    const int g = lane >> 2, t4 = lane & 3;
    const int la = lane & 15, lh = lane >> 4;

    // loader ids: thread covers 32 floats (half row) of one token
    const int ltok = tid >> 1, half = tid & 1;
    const float* qrow = g_qkv + (size_t)tok[ltok] * NQKV + half * 32;

    // ldmatrix chunk offsets (swizzle chunk c at row r -> c ^ (r&7))
    uint32_t coff[4];
#pragma unroll
    for (int q = 0; q < 4; q++)
        coff[q] = (uint32_t)((((2 * q + lh) ^ (lane & 7)) & 7) * 16);

    // ---- Phase S: S = Q K^T (accumulate over 6 c-chunks of 64) ----
    float accS[8][4];
#pragma unroll
    for (int nt = 0; nt < 8; nt++)
#pragma unroll
        for (int i = 0; i < 4; i++) accS[nt][i] = 0.f;

    const uint32_t aQh = sb + (uint32_t)((wid * 16 + la) * 128);
    const uint32_t aQl = aQh + 8192;
    const uint32_t bKh = sb + 16384 + (uint32_t)(la * 128);
    const uint32_t bKl = bKh + 8192;

    for (int cc = 0; cc < 6; cc++) {
        // load Q,K chunk -> bf16 hi/lo planes
        const float* sq = qrow + cc * 64;
        const float* sk = sq + CDIM;
#pragma unroll
        for (int i = 0; i < 8; i++) {
            const int w = half * 16 + i * 2;
            const uint32_t off = (uint32_t)(ltok * 128 +
                (((w >> 2) ^ (ltok & 7)) * 16) + (w & 3) * 4);
            float4 v = *(const float4*)(sq + i * 4);
            uint32_t h0, l0, h1, l1;
            split2(v.x, v.y, h0, l0);
            split2(v.z, v.w, h1, l1);
            *(uint2*)(asm_ + off)         = make_uint2(h0, h1);
            *(uint2*)(asm_ + 8192 + off)  = make_uint2(l0, l1);
            float4 u = *(const float4*)(sk + i * 4);
            split2(u.x, u.y, h0, l0);
            split2(u.z, u.w, h1, l1);
            *(uint2*)(asm_ + 16384 + off) = make_uint2(h0, h1);
            *(uint2*)(asm_ + 24576 + off) = make_uint2(l0, l1);
        }
        __syncthreads();
#pragma unroll
        for (int kt = 0; kt < 4; kt++) {
            uint32_t qh[4], ql[4];
            LDSM_X4(qh, aQh + coff[kt]);
            LDSM_X4(ql, aQl + coff[kt]);
#pragma unroll
            for (int ntp = 0; ntp < 4; ntp++) {
                uint32_t kh[4], kl[4];
                LDSM_X4(kh, bKh + ntp * 2048 + coff[kt]);
                LDSM_X4(kl, bKl + ntp * 2048 + coff[kt]);
                mma16816(accS[ntp * 2],     qh, kh[0], kh[2]);
                mma16816(accS[ntp * 2 + 1], qh, kh[1], kh[3]);
                mma16816(accS[ntp * 2],     ql, kh[0], kh[2]);
                mma16816(accS[ntp * 2 + 1], ql, kh[1], kh[3]);
                mma16816(accS[ntp * 2],     qh, kl[0], kl[2]);
                mma16816(accS[ntp * 2 + 1], qh, kl[1], kl[3]);
            }
        }
        __syncthreads();
    }

    // ---- S -> Ss (fp32, overlays QK region) ----
    {
        const int r0 = wid * 16 + g;
#pragma unroll
        for (int nt = 0; nt < 8; nt++) {
            const int col = nt * 8 + t4 * 2;
            Ss[r0][col]     = accS[nt][0];
            Ss[r0][col + 1] = accS[nt][1];
            Ss[r0 + 8][col]     = accS[nt][2];
            Ss[r0 + 8][col + 1] = accS[nt][3];
        }
    }
    __syncthreads();

    // ---- softmax (fp32) + P split to bf16 hi/lo planes ----
    if (tid < 64) {
        float m = -1e30f;
#pragma unroll 8
        for (int j = 0; j < 64; j++) m = fmaxf(m, Ss[tid][j]);
        float s = 0.f;
#pragma unroll 8
        for (int j = 0; j < 64; j++) {
            float e = expf(Ss[tid][j] - m);
            Ss[tid][j] = e;
            s += e;
        }
        float inv = 1.f / s;
#pragma unroll 8
        for (int j = 0; j < 64; j += 2) {
            uint32_t h, l;
            split2(Ss[tid][j] * inv, Ss[tid][j + 1] * inv, h, l);
            const int w = j >> 1;
            const uint32_t off = (uint32_t)(tid * 128 +
                (((w >> 2) ^ (tid & 7)) * 16) + (w & 3) * 4);
            *(uint32_t*)(asm_ + 32768 + off) = h;
            *(uint32_t*)(asm_ + 40960 + off) = l;
        }
    }
    __syncthreads();

    // ---- P fragments (loop-invariant across output chunks) ----
    uint32_t ph[4][4], pl[4][4];
    const uint32_t aPh = sb + 32768 + (uint32_t)((wid * 16 + la) * 128);
#pragma unroll
    for (int kt = 0; kt < 4; kt++) {
        LDSM_X4(ph[kt], aPh + coff[kt]);
        LDSM_X4(pl[kt], aPh + 8192 + coff[kt]);
    }
    const int tr0 = tok[wid * 16 + g];
    const int tr1 = tok[wid * 16 + g + 8];

    // ---- Phase O: O = P V per 64-col chunk ----
    const uint32_t bVh = sb + (uint32_t)(((((lane >> 3) & 1) * 8) + (lane & 7)) * 128);
    const uint32_t bVl = bVh + 8192;
    const float* vrow = g_qkv + (size_t)tok[ltok] * NQKV + 2 * CDIM + half * 32;

    for (int co = 0; co < 6; co++) {
        const float* sv = vrow + co * 64;
#pragma unroll
        for (int i = 0; i < 8; i++) {
            const int w = half * 16 + i * 2;
            const uint32_t off = (uint32_t)(ltok * 128 +
                (((w >> 2) ^ (ltok & 7)) * 16) + (w & 3) * 4);
            float4 v = *(const float4*)(sv + i * 4);
            uint32_t h0, l0, h1, l1;
            split2(v.x, v.y, h0, l0);
            split2(v.z, v.w, h1, l1);
            *(uint2*)(asm_ + off)        = make_uint2(h0, h1);
            *(uint2*)(asm_ + 8192 + off) = make_uint2(l0, l1);
        }
        __syncthreads();

        float accO[8][4];
#pragma unroll
        for (int nt = 0; nt < 8; nt++)
#pragma unroll
            for (int i = 0; i < 4; i++) accO[nt][i] = 0.f;

#pragma unroll
        for (int kt = 0; kt < 4; kt++) {
#pragma unroll
            for (int ntp = 0; ntp < 4; ntp++) {
                uint32_t vh[4], vl[4];
                LDSM_X4_T(vh, bVh + kt * 2048 + coff[ntp]);
                LDSM_X4_T(vl, bVl + kt * 2048 + coff[ntp]);
                mma16816(accO[ntp * 2],     ph[kt], vh[0], vh[1]);
                mma16816(accO[ntp * 2 + 1], ph[kt], vh[2], vh[3]);
                mma16816(accO[ntp * 2],     pl[kt], vh[0], vh[1]);
                mma16816(accO[ntp * 2 + 1], pl[kt], vh[2], vh[3]);
                mma16816(accO[ntp * 2],     ph[kt], vl[0], vl[1]);
                mma16816(accO[ntp * 2 + 1], ph[kt], vl[2], vl[3]);
            }
        }
#pragma unroll
        for (int nt = 0; nt < 8; nt++) {
            const int col = co * 64 + nt * 8 + t4 * 2;
            *(float2*)(g_att + (size_t)tr0 * CDIM + col) =
                make_float2(accO[nt][0], accO[nt][1]);
            *(float2*)(g_att + (size_t)tr1 * CDIM + col) =
                make_float2(accO[nt][2], accO[nt][3]);
        }
        __syncthreads();
    }
}

// ---------------------------------------------------------------------------
extern "C" void kernel_launch(void* const* d_in, const int* in_sizes, int n_in,
                              void* d_out, int out_size)
{
    const float* x      = (const float*)d_in[0];
    const float* w_qkv  = (const float*)d_in[1];
    const float* b_qkv  = (const float*)d_in[2];
    const float* w_proj = (const float*)d_in[3];
    const float* b_proj = (const float*)d_in[4];
    float* out = (float*)d_out;

    float *qkv_ptr = nullptr, *att_ptr = nullptr, *wt1 = nullptr, *wt3 = nullptr;
    cudaGetSymbolAddress((void**)&qkv_ptr, g_qkv);
    cudaGetSymbolAddress((void**)&att_ptr, g_att);
    cudaGetSymbolAddress((void**)&wt1, g_Wt1);
    cudaGetSymbolAddress((void**)&wt3, g_Wt3);

    cudaFuncSetAttribute(gemm_tf32, cudaFuncAttributeMaxDynamicSharedMemorySize,
                         3 * STAGE_BYTES);
    cudaFuncSetAttribute(window_attn, cudaFuncAttributeMaxDynamicSharedMemorySize,
                         ATTN_SMEM);

    // Weight transposes (tiny)
    trans_w_kernel<<<(NQKV * CDIM + 255) / 256, 256>>>(w_qkv, wt1, NQKV);
    trans_w_kernel<<<(CDIM * CDIM + 255) / 256, 256>>>(w_proj, wt3, CDIM);

    // K1: qkv = x @ w_qkv + b_qkv
    gemm_tf32<<<dim3(NQKV / 128, TOKENS / 128), 256, 3 * STAGE_BYTES>>>(
        x, wt1, b_qkv, qkv_ptr, NQKV);

    // K2: per-window attention (tensor-core S and PV)
    window_attn<<<NWIN, 128, ATTN_SMEM>>>();

    // K3: out = att @ w_proj + b_proj
    gemm_tf32<<<dim3(CDIM / 128, TOKENS / 128), 256, 3 * STAGE_BYTES>>>(
        att_ptr, wt3, b_proj, out, CDIM);
}

// round 10
// speedup vs baseline: 1.1265x; 1.1265x over previous
#include <cuda_runtime.h>
#include <cuda_bf16.h>
#include <cstdint>
#include <math.h>

// Problem constants (B=8, H=W=128, C=384, window=8)
#define TOKENS   131072              // 8*128*128
#define CDIM     384
#define NQKV     1152
#define NWIN     2048                // 8 * 16 * 16 windows

// ---------------------------------------------------------------------------
// Scratch (allocation-free rule: __device__ globals)
// g_qkv2 per-token layout (bf16): [q hi 384][q lo 384][k hi][k lo][v hi][v lo]
// ---------------------------------------------------------------------------
__device__ __nv_bfloat16 g_qkv2[(size_t)TOKENS * 2304];  // 604 MB
__device__ float g_att[(size_t)TOKENS * CDIM];           // fp32 attention out
__device__ float g_Wt1[(size_t)NQKV * CDIM];             // w_qkv^T  tf32-rounded
__device__ float g_Wt3[(size_t)CDIM * CDIM];             // w_proj^T tf32-rounded

__device__ __forceinline__ uint32_t smem_u32(const void* p) {
    uint32_t a;
    asm("{ .reg .u64 tmp; cvta.to.shared.u64 tmp, %1; cvt.u32.u64 %0, tmp; }"
        : "=r"(a) : "l"(p));
    return a;
}

// Split a float2 into packed bf16x2 hi and lo (residual) parts.
__device__ __forceinline__ void split2(float x, float y, uint32_t& hi, uint32_t& lo) {
    uint32_t h;
    asm("cvt.rn.bf16x2.f32 %0, %1, %2;" : "=r"(h) : "f"(y), "f"(x));
    float h0 = __uint_as_float(h << 16);
    float h1 = __uint_as_float(h & 0xffff0000u);
    float r0 = x - h0, r1 = y - h1;
    asm("cvt.rn.bf16x2.f32 %0, %1, %2;" : "=r"(lo) : "f"(r1), "f"(r0));
    hi = h;
}

__device__ __forceinline__ void mma_tf32(float* c, const uint32_t* a,
                                         uint32_t b0, uint32_t b1) {
    asm volatile(
        "mma.sync.aligned.m16n8k8.row.col.f32.tf32.tf32.f32 "
        "{%0,%1,%2,%3}, {%4,%5,%6,%7}, {%8,%9}, {%0,%1,%2,%3};\n"
        : "+f"(c[0]), "+f"(c[1]), "+f"(c[2]), "+f"(c[3])
        : "r"(a[0]), "r"(a[1]), "r"(a[2]), "r"(a[3]), "r"(b0), "r"(b1));
}

__device__ __forceinline__ void mma16816(float* c, const uint32_t* a,
                                         uint32_t b0, uint32_t b1) {
    asm volatile(
        "mma.sync.aligned.m16n8k16.row.col.f32.bf16.bf16.f32 "
        "{%0,%1,%2,%3}, {%4,%5,%6,%7}, {%8,%9}, {%0,%1,%2,%3};\n"
        : "+f"(c[0]), "+f"(c[1]), "+f"(c[2]), "+f"(c[3])
        : "r"(a[0]), "r"(a[1]), "r"(a[2]), "r"(a[3]), "r"(b0), "r"(b1));
}

#define LDSM_X4(r, a) \
    asm volatile("ldmatrix.sync.aligned.m8n8.x4.shared.b16 {%0,%1,%2,%3}, [%4];" \
        : "=r"((r)[0]), "=r"((r)[1]), "=r"((r)[2]), "=r"((r)[3]) : "r"(a))

#define LDSM_X4_T(r, a) \
    asm volatile("ldmatrix.sync.aligned.m8n8.x4.trans.shared.b16 {%0,%1,%2,%3}, [%4];" \
        : "=r"((r)[0]), "=r"((r)[1]), "=r"((r)[2]), "=r"((r)[3]) : "r"(a))

#define CVT_TF32(r) \
    asm("cvt.rna.tf32.f32 %0, %0;" : "+r"(r))

// ---------------------------------------------------------------------------
// Weight transpose + tf32 rounding: w [384 x N] fp32 -> out [N x 384]
// ---------------------------------------------------------------------------
__global__ __launch_bounds__(256) void trans_w_kernel(
    const float* __restrict__ w, float* __restrict__ out, int N)
{
    const int t = blockIdx.x * 256 + threadIdx.x;
    if (t >= N * CDIM) return;
    const int n = t / CDIM;
    const int k = t % CDIM;
    uint32_t v = __float_as_uint(w[(size_t)k * N + n]);
    CVT_TF32(v);
    out[(size_t)n * CDIM + k] = __uint_as_float(v);
}

// ---------------------------------------------------------------------------
// TF32 GEMM (validated). If Csplit != 0, epilogue writes split-bf16 hi/lo
// planes into g_qkv2-format [token][2304] instead of fp32 C.
// ---------------------------------------------------------------------------
#define STAGE_BYTES 32768u
__global__ __launch_bounds__(256, 2) void gemm_tf32(
    const float* __restrict__ A,
    const float* __restrict__ Bt,
    const float* __restrict__ bias,
    float* __restrict__ C,
    __nv_bfloat16* __restrict__ Csplit,
    int Ndim)
{
    extern __shared__ __align__(16) char smem[];
    const uint32_t smemBase = smem_u32(smem);

    const int tid  = threadIdx.x;
    const int wid  = tid >> 5;
    const int lane = tid & 31;
    const int g    = lane >> 2;
    const int t4   = lane & 3;
    const int m0   = blockIdx.y * 128;
    const int n0   = blockIdx.x * 128;
    const int wm   = (wid & 3) * 32;
    const int wn   = (wid >> 2) * 64;

    const float* srcs[8];
    uint32_t dsts[8];
#pragma unroll
    for (int i = 0; i < 8; i++) {
        const int id = tid + i * 256;
        const int ab = id >> 10;
        const int r  = (id >> 3) & 127;
        const int ch = id & 7;
        if (ab == 0) srcs[i] = A  + (size_t)(m0 + r) * CDIM + ch * 4;
        else         srcs[i] = Bt + (size_t)(n0 + r) * CDIM + ch * 4;
        dsts[i] = smemBase + (uint32_t)(ab * 16384 + r * 128 + (ch ^ (r & 7)) * 16);
    }

#define PREFETCH(s, off) do {                                                 \
        _Pragma("unroll")                                                     \
        for (int _i = 0; _i < 8; _i++) {                                      \
            asm volatile("cp.async.cg.shared.global [%0], [%1], 16;"          \
                :: "r"(dsts[_i] + (off)), "l"(srcs[_i] + (s) * 32));          \
        }                                                                     \
        asm volatile("cp.async.commit_group;" ::: "memory");                  \
    } while (0)

    const int la = lane & 15;
    const int h  = lane >> 4;
    const int s7 = la & 7;
    uint32_t coff[4];
#pragma unroll
    for (int q = 0; q < 4; q++)
        coff[q] = (uint32_t)((((2 * q + h) ^ s7) & 7) * 16);
    const uint32_t aBase = smemBase + (uint32_t)((wm + la) * 128);
    const uint32_t bBase = smemBase + 16384 + (uint32_t)((wn + la) * 128);

    float acc[2][8][4];
#pragma unroll
    for (int mt = 0; mt < 2; mt++)
#pragma unroll
        for (int nt = 0; nt < 8; nt++)
#pragma unroll
            for (int i = 0; i < 4; i++) acc[mt][nt][i] = 0.f;

    PREFETCH(0, 0);
    PREFETCH(1, STAGE_BYTES);

#pragma unroll
    for (int s = 0; s < 12; s++) {
        asm volatile("cp.async.wait_group 1;" ::: "memory");
        __syncthreads();
        if (s < 10) PREFETCH(s + 2, ((s + 2) % 3) * STAGE_BYTES);
        else asm volatile("cp.async.commit_group;" ::: "memory");
        const uint32_t off = (s % 3) * STAGE_BYTES;

#pragma unroll
        for (int q = 0; q < 4; q++) {
            uint32_t a[2][4];
#pragma unroll
            for (int mt = 0; mt < 2; mt++) {
                LDSM_X4(a[mt], aBase + off + mt * 2048 + coff[q]);
                CVT_TF32(a[mt][0]); CVT_TF32(a[mt][1]);
                CVT_TF32(a[mt][2]); CVT_TF32(a[mt][3]);
            }
#pragma unroll
            for (int ntp = 0; ntp < 4; ntp++) {
                uint32_t b[4];
                LDSM_X4(b, bBase + off + ntp * 2048 + coff[q]);
                mma_tf32(acc[0][ntp * 2],     a[0], b[0], b[2]);
                mma_tf32(acc[0][ntp * 2 + 1], a[0], b[1], b[3]);
                mma_tf32(acc[1][ntp * 2],     a[1], b[0], b[2]);
                mma_tf32(acc[1][ntp * 2 + 1], a[1], b[1], b[3]);
            }
        }
    }
#undef PREFETCH

#pragma unroll
    for (int mt = 0; mt < 2; mt++) {
        const int r0 = m0 + wm + mt * 16 + g;
#pragma unroll
        for (int nt = 0; nt < 8; nt++) {
            const int col = n0 + wn + (nt >> 1) * 16 + (nt & 1) * 8 + t4 * 2;
            float2 bv = *(const float2*)(bias + col);
            float2 v0 = make_float2(acc[mt][nt][0] + bv.x, acc[mt][nt][1] + bv.y);
            float2 v1 = make_float2(acc[mt][nt][2] + bv.x, acc[mt][nt][3] + bv.y);
            if (Csplit) {
                const int pl = col / 384;
                const int wi = col - pl * 384;
                uint32_t hh, ll;
                __nv_bfloat16* b0 = Csplit + (size_t)r0 * 2304 + pl * 768 + wi;
                split2(v0.x, v0.y, hh, ll);
                *(uint32_t*)(b0)       = hh;
                *(uint32_t*)(b0 + 384) = ll;
                __nv_bfloat16* b1 = Csplit + (size_t)(r0 + 8) * 2304 + pl * 768 + wi;
                split2(v1.x, v1.y, hh, ll);
                *(uint32_t*)(b1)       = hh;
                *(uint32_t*)(b1 + 384) = ll;
            } else {
                *(float2*)(C + (size_t)r0 * Ndim + col) = v0;
                *(float2*)(C + (size_t)(r0 + 8) * Ndim + col) = v1;
            }
        }
    }
}

// ---------------------------------------------------------------------------
// Window attention v3: split-bf16 HMMA (r9 layout, validated) + cp.async
// double-buffered plane loads, no in-kernel QKV conversion.
//   smem: stage0 [0,32K) = Qh|Ql|Kh|Kl chunk planes (8KB each)
//         stage1 [32K,64K); O phase reuses stages for Vh|Vl (8KB each)
//         P planes [64K,80K); Ss fp32 [64][65] overlays stage0; tok @80K.
// ---------------------------------------------------------------------------
#define ATTN_SMEM 82432
__global__ __launch_bounds__(128) void window_attn()
{
    extern __shared__ __align__(16) char asm_[];
    const uint32_t sb = smem_u32(asm_);
    int* tok = (int*)(asm_ + 81920);
    float (*Ss)[65] = (float(*)[65])asm_;

    const int gb = blockIdx.x;
    const int b = gb >> 8, win = gb & 255, wy = win >> 4, wx = win & 15;
    const int tid = threadIdx.x;
    if (tid < 64) {
        int py = tid >> 3, px = tid & 7;
        tok[tid] = b * 16384 + (wy * 8 + py) * 128 + (wx * 8 + px);
    }
    __syncthreads();

    const int wid = tid >> 5, lane = tid & 31;
    const int g = lane >> 2, t4 = lane & 3;
    const int la = lane & 15, lh = lane >> 4;

    // ldmatrix chunk offsets (swizzle chunk c at row r -> c ^ (r&7))
    uint32_t coff[4];
#pragma unroll
    for (int q = 0; q < 4; q++)
        coff[q] = (uint32_t)((((2 * q + lh) ^ (lane & 7)) & 7) * 16);

    // ---- S-phase cp.async descriptors: 16 x 16B chunks per thread ----
    // planes p: 0=Qh 1=Ql 2=Kh 3=Kl ; row t (token), 8 chunks of 16B per row
    const __nv_bfloat16* sQK[16];
    uint32_t dQK[16];
#pragma unroll
    for (int i = 0; i < 16; i++) {
        const int id = tid + i * 128;          // < 2048
        const int p  = id >> 9;
        const int t  = (id >> 3) & 63;
        const int ci = id & 7;
        sQK[i] = g_qkv2 + (size_t)tok[t] * 2304 + p * 384 + ci * 8;
        dQK[i] = sb + (uint32_t)(p * 8192 + t * 128 + ((ci ^ (t & 7)) * 16));
    }

#define PREF_QK(cc) do {                                                      \
        const uint32_t _o = ((cc) & 1) * 32768u;                              \
        _Pragma("unroll")                                                     \
        for (int _i = 0; _i < 16; _i++) {                                     \
            asm volatile("cp.async.cg.shared.global [%0], [%1], 16;"          \
                :: "r"(dQK[_i] + _o), "l"(sQK[_i] + (cc) * 64));              \
        }                                                                     \
        asm volatile("cp.async.commit_group;" ::: "memory");                  \
    } while (0)

    // ---- Phase S: S = Q K^T, 6 chunks of 64 cols ----
    float accS[8][4];
#pragma unroll
    for (int nt = 0; nt < 8; nt++)
#pragma unroll
        for (int i = 0; i < 4; i++) accS[nt][i] = 0.f;

    PREF_QK(0);

#pragma unroll
    for (int cc = 0; cc < 6; cc++) {
        asm volatile("cp.async.wait_group 0;" ::: "memory");
        __syncthreads();
        if (cc < 5) PREF_QK(cc + 1);
        const uint32_t st = (cc & 1) * 32768u;
        const uint32_t aQh = sb + st + (uint32_t)((wid * 16 + la) * 128);
        const uint32_t aQl = aQh + 8192;
        const uint32_t bKh = sb + st + 16384 + (uint32_t)(la * 128);
        const uint32_t bKl = bKh + 8192;
#pragma unroll
        for (int kt = 0; kt < 4; kt++) {
            uint32_t qh[4], ql[4];
            LDSM_X4(qh, aQh + coff[kt]);
            LDSM_X4(ql, aQl + coff[kt]);
#pragma unroll
            for (int ntp = 0; ntp < 4; ntp++) {
                uint32_t kh[4], kl[4];
                LDSM_X4(kh, bKh + ntp * 2048 + coff[kt]);
                LDSM_X4(kl, bKl + ntp * 2048 + coff[kt]);
                mma16816(accS[ntp * 2],     qh, kh[0], kh[2]);
                mma16816(accS[ntp * 2 + 1], qh, kh[1], kh[3]);
                mma16816(accS[ntp * 2],     ql, kh[0], kh[2]);
                mma16816(accS[ntp * 2 + 1], ql, kh[1], kh[3]);
                mma16816(accS[ntp * 2],     qh, kl[0], kl[2]);
                mma16816(accS[ntp * 2 + 1], qh, kl[1], kl[3]);
            }
        }
    }
#undef PREF_QK
    __syncthreads();

    // ---- S -> Ss (fp32, overlays stage0) ----
    {
        const int r0 = wid * 16 + g;
#pragma unroll
        for (int nt = 0; nt < 8; nt++) {
            const int col = nt * 8 + t4 * 2;
            Ss[r0][col]         = accS[nt][0];
            Ss[r0][col + 1]     = accS[nt][1];
            Ss[r0 + 8][col]     = accS[nt][2];
            Ss[r0 + 8][col + 1] = accS[nt][3];
        }
    }
    __syncthreads();

    // ---- softmax (fp32) + P split to bf16 hi/lo planes at 80K-16K=65536 ----
    if (tid < 64) {
        float m = -1e30f;
#pragma unroll 8
        for (int j = 0; j < 64; j++) m = fmaxf(m, Ss[tid][j]);
        float s = 0.f;
#pragma unroll 8
        for (int j = 0; j < 64; j++) {
            float e = expf(Ss[tid][j] - m);
            Ss[tid][j] = e;
            s += e;
        }
        float inv = 1.f / s;
#pragma unroll 8
        for (int j = 0; j < 64; j += 2) {
            uint32_t hh, ll;
            split2(Ss[tid][j] * inv, Ss[tid][j + 1] * inv, hh, ll);
            const int w = j >> 1;
            const uint32_t off = (uint32_t)(tid * 128 +
                (((w >> 2) ^ (tid & 7)) * 16) + (w & 3) * 4);
            *(uint32_t*)(asm_ + 65536 + off) = hh;
            *(uint32_t*)(asm_ + 73728 + off) = ll;
        }
    }
    __syncthreads();

    // ---- P fragments (loop-invariant) ----
    uint32_t ph[4][4], pl[4][4];
    const uint32_t aPh = sb + 65536 + (uint32_t)((wid * 16 + la) * 128);
#pragma unroll
    for (int kt = 0; kt < 4; kt++) {
        LDSM_X4(ph[kt], aPh + coff[kt]);
        LDSM_X4(pl[kt], aPh + 8192 + coff[kt]);
    }
    const int tr0 = tok[wid * 16 + g];
    const int tr1 = tok[wid * 16 + g + 8];

    // ---- O-phase cp.async descriptors: 8 chunks per thread ----
    const __nv_bfloat16* sV[8];
    uint32_t dV[8];
#pragma unroll
    for (int i = 0; i < 8; i++) {
        const int id = tid + i * 128;          // < 1024
        const int p  = id >> 9;                // 0=Vh 1=Vl
        const int t  = (id >> 3) & 63;
        const int ci = id & 7;
        sV[i] = g_qkv2 + (size_t)tok[t] * 2304 + 1536 + p * 384 + ci * 8;
        dV[i] = sb + (uint32_t)(p * 8192 + t * 128 + ((ci ^ (t & 7)) * 16));
    }

#define PREF_V(co) do {                                                       \
        const uint32_t _o = ((co) & 1) * 32768u;                              \
        _Pragma("unroll")                                                     \
        for (int _i = 0; _i < 8; _i++) {                                      \
            asm volatile("cp.async.cg.shared.global [%0], [%1], 16;"          \
                :: "r"(dV[_i] + _o), "l"(sV[_i] + (co) * 64));                \
        }                                                                     \
        asm volatile("cp.async.commit_group;" ::: "memory");                  \
    } while (0)

    PREF_V(0);

    const uint32_t vbase = sb + (uint32_t)(((((lane >> 3) & 1) * 8) + (lane & 7)) * 128);

#pragma unroll
    for (int co = 0; co < 6; co++) {
        asm volatile("cp.async.wait_group 0;" ::: "memory");
        __syncthreads();
        if (co < 5) PREF_V(co + 1);
        const uint32_t st = (co & 1) * 32768u;
        const uint32_t bVh = vbase + st;
        const uint32_t bVl = bVh + 8192;

        float accO[8][4];
#pragma unroll
        for (int nt = 0; nt < 8; nt++)
#pragma unroll
            for (int i = 0; i < 4; i++) accO[nt][i] = 0.f;

#pragma unroll
        for (int kt = 0; kt < 4; kt++) {
#pragma unroll
            for (int ntp = 0; ntp < 4; ntp++) {
                uint32_t vh[4], vl[4];
                LDSM_X4_T(vh, bVh + kt * 2048 + coff[ntp]);
                LDSM_X4_T(vl, bVl + kt * 2048 + coff[ntp]);
                mma16816(accO[ntp * 2],     ph[kt], vh[0], vh[1]);
                mma16816(accO[ntp * 2 + 1], ph[kt], vh[2], vh[3]);
                mma16816(accO[ntp * 2],     pl[kt], vh[0], vh[1]);
                mma16816(accO[ntp * 2 + 1], pl[kt], vh[2], vh[3]);
                mma16816(accO[ntp * 2],     ph[kt], vl[0], vl[1]);
                mma16816(accO[ntp * 2 + 1], ph[kt], vl[2], vl[3]);
            }
        }
#pragma unroll
        for (int nt = 0; nt < 8; nt++) {
            const int col = co * 64 + nt * 8 + t4 * 2;
            *(float2*)(g_att + (size_t)tr0 * CDIM + col) =
                make_float2(accO[nt][0], accO[nt][1]);
            *(float2*)(g_att + (size_t)tr1 * CDIM + col) =
                make_float2(accO[nt][2], accO[nt][3]);
        }
    }
#undef PREF_V
}

// ---------------------------------------------------------------------------
extern "C" void kernel_launch(void* const* d_in, const int* in_sizes, int n_in,
                              void* d_out, int out_size)
{
    const float* x      = (const float*)d_in[0];
    const float* w_qkv  = (const float*)d_in[1];
    const float* b_qkv  = (const float*)d_in[2];
    const float* w_proj = (const float*)d_in[3];
    const float* b_proj = (const float*)d_in[4];
    float* out = (float*)d_out;

    float *att_ptr = nullptr, *wt1 = nullptr, *wt3 = nullptr;
    __nv_bfloat16* qkv2 = nullptr;
    cudaGetSymbolAddress((void**)&qkv2,   g_qkv2);
    cudaGetSymbolAddress((void**)&att_ptr, g_att);
    cudaGetSymbolAddress((void**)&wt1, g_Wt1);
    cudaGetSymbolAddress((void**)&wt3, g_Wt3);

    cudaFuncSetAttribute(gemm_tf32, cudaFuncAttributeMaxDynamicSharedMemorySize,
                         3 * STAGE_BYTES);
    cudaFuncSetAttribute(window_attn, cudaFuncAttributeMaxDynamicSharedMemorySize,
                         ATTN_SMEM);

    // Weight transposes (tiny)
    trans_w_kernel<<<(NQKV * CDIM + 255) / 256, 256>>>(w_qkv, wt1, NQKV);
    trans_w_kernel<<<(CDIM * CDIM + 255) / 256, 256>>>(w_proj, wt3, CDIM);

    // K1: qkv = x @ w_qkv + b_qkv  -> split-bf16 planes (g_qkv2)
    gemm_tf32<<<dim3(NQKV / 128, TOKENS / 128), 256, 3 * STAGE_BYTES>>>(
        x, wt1, b_qkv, nullptr, qkv2, NQKV);

    // K2: per-window attention (tensor S and PV; zero conversions)
    window_attn<<<NWIN, 128, ATTN_SMEM>>>();

    // K3: out = att @ w_proj + b_proj (fp32 out)
    gemm_tf32<<<dim3(CDIM / 128, TOKENS / 128), 256, 3 * STAGE_BYTES>>>(
        att_ptr, wt3, b_proj, out, nullptr, CDIM);
}

// round 11
// speedup vs baseline: 1.5713x; 1.3949x over previous
#include <cuda_runtime.h>
#include <cuda_bf16.h>
#include <cuda_fp16.h>
#include <cstdint>
#include <math.h>

// Problem constants (B=8, H=W=128, C=384, window=8)
#define TOKENS   131072              // 8*128*128
#define CDIM     384
#define NQKV     1152
#define NWIN     2048                // 8 * 16 * 16 windows

// ---------------------------------------------------------------------------
// Scratch (allocation-free rule: __device__ globals)
// g_qkv2 per-token layout (bf16): [q hi 384][q lo 384][k hi][k lo][v hi][v lo]
// ---------------------------------------------------------------------------
__device__ __nv_bfloat16 g_qkv2[(size_t)TOKENS * 2304];  // 604 MB
__device__ __half g_att_h[(size_t)TOKENS * CDIM];        // fp16 attention out (100 MB)
__device__ __half g_xh [(size_t)TOKENS * CDIM];          // fp16 x (100 MB)
__device__ __half g_Wt1[(size_t)NQKV * CDIM];            // w_qkv^T  fp16 [N][K]
__device__ __half g_Wt3[(size_t)CDIM * CDIM];            // w_proj^T fp16 [N][K]

__device__ __forceinline__ uint32_t smem_u32(const void* p) {
    uint32_t a;
    asm("{ .reg .u64 tmp; cvta.to.shared.u64 tmp, %1; cvt.u32.u64 %0, tmp; }"
        : "=r"(a) : "l"(p));
    return a;
}

// Split a float2 into packed bf16x2 hi and lo (residual) parts.
__device__ __forceinline__ void split2(float x, float y, uint32_t& hi, uint32_t& lo) {
    uint32_t h;
    asm("cvt.rn.bf16x2.f32 %0, %1, %2;" : "=r"(h) : "f"(y), "f"(x));
    float h0 = __uint_as_float(h << 16);
    float h1 = __uint_as_float(h & 0xffff0000u);
    float r0 = x - h0, r1 = y - h1;
    asm("cvt.rn.bf16x2.f32 %0, %1, %2;" : "=r"(lo) : "f"(r1), "f"(r0));
    hi = h;
}

// bf16 HMMA (attention — validated)
__device__ __forceinline__ void mma16816(float* c, const uint32_t* a,
                                         uint32_t b0, uint32_t b1) {
    asm volatile(
        "mma.sync.aligned.m16n8k16.row.col.f32.bf16.bf16.f32 "
        "{%0,%1,%2,%3}, {%4,%5,%6,%7}, {%8,%9}, {%0,%1,%2,%3};\n"
        : "+f"(c[0]), "+f"(c[1]), "+f"(c[2]), "+f"(c[3])
        : "r"(a[0]), "r"(a[1]), "r"(a[2]), "r"(a[3]), "r"(b0), "r"(b1));
}

// fp16 HMMA (GEMMs)
__device__ __forceinline__ void mma16816h(float* c, const uint32_t* a,
                                          uint32_t b0, uint32_t b1) {
    asm volatile(
        "mma.sync.aligned.m16n8k16.row.col.f32.f16.f16.f32 "
        "{%0,%1,%2,%3}, {%4,%5,%6,%7}, {%8,%9}, {%0,%1,%2,%3};\n"
        : "+f"(c[0]), "+f"(c[1]), "+f"(c[2]), "+f"(c[3])
        : "r"(a[0]), "r"(a[1]), "r"(a[2]), "r"(a[3]), "r"(b0), "r"(b1));
}

#define LDSM_X4(r, a) \
    asm volatile("ldmatrix.sync.aligned.m8n8.x4.shared.b16 {%0,%1,%2,%3}, [%4];" \
        : "=r"((r)[0]), "=r"((r)[1]), "=r"((r)[2]), "=r"((r)[3]) : "r"(a))

#define LDSM_X4_T(r, a) \
    asm volatile("ldmatrix.sync.aligned.m8n8.x4.trans.shared.b16 {%0,%1,%2,%3}, [%4];" \
        : "=r"((r)[0]), "=r"((r)[1]), "=r"((r)[2]), "=r"((r)[3]) : "r"(a))

// ---------------------------------------------------------------------------
// Weight transpose -> fp16: w [384 x N] fp32 -> out [N x 384] fp16
// ---------------------------------------------------------------------------
__global__ __launch_bounds__(256) void trans_w_kernel(
    const float* __restrict__ w, __half* __restrict__ out, int N)
{
    const int t = blockIdx.x * 256 + threadIdx.x;
    if (t >= N * CDIM) return;
    const int n = t / CDIM;
    const int k = t % CDIM;
    out[(size_t)n * CDIM + k] = __float2half(w[(size_t)k * N + n]);
}

// ---------------------------------------------------------------------------
// fp32 -> fp16 bulk convert (x)
// ---------------------------------------------------------------------------
__global__ __launch_bounds__(256) void cvt_h_kernel(
    const float* __restrict__ in, __half* __restrict__ out)
{
    const size_t t = (size_t)blockIdx.x * 256 + threadIdx.x;   // < TOKENS*96
    float4 v = *(const float4*)(in + t * 4);
    __half2 a = __floats2half2_rn(v.x, v.y);
    __half2 b = __floats2half2_rn(v.z, v.w);
    *(uint2*)(out + t * 4) = make_uint2(
        *(uint32_t*)&a, *(uint32_t*)&b);
}

// ---------------------------------------------------------------------------
// fp16 GEMM: C[M x Ndim] = A[M x 384](fp16) @ Bt^T + bias.
//   BM=128, BN=128, BK=64 halfs (128B rows), 256 threads (8 warps 4M x 2N),
//   2 CTAs/SM. Stage = 32768 B, 3 stages, 6 K-iterations.
//   If Csplit != 0: epilogue writes split-bf16 planes (g_qkv2 layout).
// ---------------------------------------------------------------------------
#define STAGE_BYTES 32768u
__global__ __launch_bounds__(256, 2) void gemm_h(
    const __half* __restrict__ A,
    const __half* __restrict__ Bt,
    const float* __restrict__ bias,
    float* __restrict__ C,
    __nv_bfloat16* __restrict__ Csplit,
    int Ndim)
{
    extern __shared__ __align__(16) char smem[];
    const uint32_t smemBase = smem_u32(smem);

    const int tid  = threadIdx.x;
    const int wid  = tid >> 5;
    const int lane = tid & 31;
    const int g    = lane >> 2;
    const int t4   = lane & 3;
    const int m0   = blockIdx.y * 128;
    const int n0   = blockIdx.x * 128;
    const int wm   = (wid & 3) * 32;
    const int wn   = (wid >> 2) * 64;

    // cp.async: 2048 chunks of 16B per stage (A 1024 + B 1024); 8 per thread
    const __half* srcs[8];
    uint32_t dsts[8];
#pragma unroll
    for (int i = 0; i < 8; i++) {
        const int id = tid + i * 256;
        const int ab = id >> 10;
        const int r  = (id >> 3) & 127;
        const int ch = id & 7;
        if (ab == 0) srcs[i] = A  + (size_t)(m0 + r) * CDIM + ch * 8;
        else         srcs[i] = Bt + (size_t)(n0 + r) * CDIM + ch * 8;
        dsts[i] = smemBase + (uint32_t)(ab * 16384 + r * 128 + ((ch ^ (r & 7)) * 16));
    }

#define PREFETCH(s, off) do {                                                 \
        _Pragma("unroll")                                                     \
        for (int _i = 0; _i < 8; _i++) {                                      \
            asm volatile("cp.async.cg.shared.global [%0], [%1], 16;"          \
                :: "r"(dsts[_i] + (off)), "l"(srcs[_i] + (s) * 64));          \
        }                                                                     \
        asm volatile("cp.async.commit_group;" ::: "memory");                  \
    } while (0)

    // ldmatrix: lane row la, k16-step q -> chunk 2q + (lane>>4), swizzled
    const int la = lane & 15;
    const int h  = lane >> 4;
    const int s7 = la & 7;
    uint32_t coff[4];
#pragma unroll
    for (int q = 0; q < 4; q++)
        coff[q] = (uint32_t)((((2 * q + h) ^ s7) & 7) * 16);
    const uint32_t aBase = smemBase + (uint32_t)((wm + la) * 128);
    const uint32_t bBase = smemBase + 16384 + (uint32_t)((wn + la) * 128);

    float acc[2][8][4];
#pragma unroll
    for (int mt = 0; mt < 2; mt++)
#pragma unroll
        for (int nt = 0; nt < 8; nt++)
#pragma unroll
            for (int i = 0; i < 4; i++) acc[mt][nt][i] = 0.f;

    PREFETCH(0, 0);
    PREFETCH(1, STAGE_BYTES);

#pragma unroll
    for (int s = 0; s < 6; s++) {
        asm volatile("cp.async.wait_group 1;" ::: "memory");
        __syncthreads();
        if (s < 4) PREFETCH(s + 2, ((s + 2) % 3) * STAGE_BYTES);
        else asm volatile("cp.async.commit_group;" ::: "memory");
        const uint32_t off = (s % 3) * STAGE_BYTES;

#pragma unroll
        for (int q = 0; q < 4; q++) {              // 4 x k16 per stage
            uint32_t a[2][4];
#pragma unroll
            for (int mt = 0; mt < 2; mt++)
                LDSM_X4(a[mt], aBase + off + mt * 2048 + coff[q]);
#pragma unroll
            for (int ntp = 0; ntp < 4; ntp++) {
                uint32_t b[4];
                LDSM_X4(b, bBase + off + ntp * 2048 + coff[q]);
                mma16816h(acc[0][ntp * 2],     a[0], b[0], b[2]);
                mma16816h(acc[0][ntp * 2 + 1], a[0], b[1], b[3]);
                mma16816h(acc[1][ntp * 2],     a[1], b[0], b[2]);
                mma16816h(acc[1][ntp * 2 + 1], a[1], b[1], b[3]);
            }
        }
    }
#undef PREFETCH

#pragma unroll
    for (int mt = 0; mt < 2; mt++) {
        const int r0 = m0 + wm + mt * 16 + g;
#pragma unroll
        for (int nt = 0; nt < 8; nt++) {
            const int col = n0 + wn + (nt >> 1) * 16 + (nt & 1) * 8 + t4 * 2;
            float2 bv = *(const float2*)(bias + col);
            float2 v0 = make_float2(acc[mt][nt][0] + bv.x, acc[mt][nt][1] + bv.y);
            float2 v1 = make_float2(acc[mt][nt][2] + bv.x, acc[mt][nt][3] + bv.y);
            if (Csplit) {
                const int pl = col / 384;
                const int wi = col - pl * 384;
                uint32_t hh, ll;
                __nv_bfloat16* b0 = Csplit + (size_t)r0 * 2304 + pl * 768 + wi;
                split2(v0.x, v0.y, hh, ll);
                *(uint32_t*)(b0)       = hh;
                *(uint32_t*)(b0 + 384) = ll;
                __nv_bfloat16* b1 = Csplit + (size_t)(r0 + 8) * 2304 + pl * 768 + wi;
                split2(v1.x, v1.y, hh, ll);
                *(uint32_t*)(b1)       = hh;
                *(uint32_t*)(b1 + 384) = ll;
            } else {
                *(float2*)(C + (size_t)r0 * Ndim + col) = v0;
                *(float2*)(C + (size_t)(r0 + 8) * Ndim + col) = v1;
            }
        }
    }
}

// ---------------------------------------------------------------------------
// Window attention (r10, validated) — only change: fp16 output stores.
// ---------------------------------------------------------------------------
#define ATTN_SMEM 82432
__global__ __launch_bounds__(128) void window_attn()
{
    extern __shared__ __align__(16) char asm_[];
    const uint32_t sb = smem_u32(asm_);
    int* tok = (int*)(asm_ + 81920);
    float (*Ss)[65] = (float(*)[65])asm_;

    const int gb = blockIdx.x;
    const int b = gb >> 8, win = gb & 255, wy = win >> 4, wx = win & 15;
    const int tid = threadIdx.x;
    if (tid < 64) {
        int py = tid >> 3, px = tid & 7;
        tok[tid] = b * 16384 + (wy * 8 + py) * 128 + (wx * 8 + px);
    }
    __syncthreads();

    const int wid = tid >> 5, lane = tid & 31;
    const int g = lane >> 2, t4 = lane & 3;
    const int la = lane & 15, lh = lane >> 4;

    uint32_t coff[4];
#pragma unroll
    for (int q = 0; q < 4; q++)
        coff[q] = (uint32_t)((((2 * q + lh) ^ (lane & 7)) & 7) * 16);

    // ---- S-phase cp.async descriptors ----
    const __nv_bfloat16* sQK[16];
    uint32_t dQK[16];
#pragma unroll
    for (int i = 0; i < 16; i++) {
        const int id = tid + i * 128;
        const int p  = id >> 9;
        const int t  = (id >> 3) & 63;
        const int ci = id & 7;
        sQK[i] = g_qkv2 + (size_t)tok[t] * 2304 + p * 384 + ci * 8;
        dQK[i] = sb + (uint32_t)(p * 8192 + t * 128 + ((ci ^ (t & 7)) * 16));
    }

#define PREF_QK(cc) do {                                                      \
        const uint32_t _o = ((cc) & 1) * 32768u;                              \
        _Pragma("unroll")                                                     \
        for (int _i = 0; _i < 16; _i++) {                                     \
            asm volatile("cp.async.cg.shared.global [%0], [%1], 16;"          \
                :: "r"(dQK[_i] + _o), "l"(sQK[_i] + (cc) * 64));              \
        }                                                                     \
        asm volatile("cp.async.commit_group;" ::: "memory");                  \
    } while (0)

    float accS[8][4];
#pragma unroll
    for (int nt = 0; nt < 8; nt++)
#pragma unroll
        for (int i = 0; i < 4; i++) accS[nt][i] = 0.f;

    PREF_QK(0);

#pragma unroll
    for (int cc = 0; cc < 6; cc++) {
        asm volatile("cp.async.wait_group 0;" ::: "memory");
        __syncthreads();
        if (cc < 5) PREF_QK(cc + 1);
        const uint32_t st = (cc & 1) * 32768u;
        const uint32_t aQh = sb + st + (uint32_t)((wid * 16 + la) * 128);
        const uint32_t aQl = aQh + 8192;
        const uint32_t bKh = sb + st + 16384 + (uint32_t)(la * 128);
        const uint32_t bKl = bKh + 8192;
#pragma unroll
        for (int kt = 0; kt < 4; kt++) {
            uint32_t qh[4], ql[4];
            LDSM_X4(qh, aQh + coff[kt]);
            LDSM_X4(ql, aQl + coff[kt]);
#pragma unroll
            for (int ntp = 0; ntp < 4; ntp++) {
                uint32_t kh[4], kl[4];
                LDSM_X4(kh, bKh + ntp * 2048 + coff[kt]);
                LDSM_X4(kl, bKl + ntp * 2048 + coff[kt]);
                mma16816(accS[ntp * 2],     qh, kh[0], kh[2]);
                mma16816(accS[ntp * 2 + 1], qh, kh[1], kh[3]);
                mma16816(accS[ntp * 2],     ql, kh[0], kh[2]);
                mma16816(accS[ntp * 2 + 1], ql, kh[1], kh[3]);
                mma16816(accS[ntp * 2],     qh, kl[0], kl[2]);
                mma16816(accS[ntp * 2 + 1], qh, kl[1], kl[3]);
            }
        }
    }
#undef PREF_QK
    __syncthreads();

    {
        const int r0 = wid * 16 + g;
#pragma unroll
        for (int nt = 0; nt < 8; nt++) {
            const int col = nt * 8 + t4 * 2;
            Ss[r0][col]         = accS[nt][0];
            Ss[r0][col + 1]     = accS[nt][1];
            Ss[r0 + 8][col]     = accS[nt][2];
            Ss[r0 + 8][col + 1] = accS[nt][3];
        }
    }
    __syncthreads();

    if (tid < 64) {
        float m = -1e30f;
#pragma unroll 8
        for (int j = 0; j < 64; j++) m = fmaxf(m, Ss[tid][j]);
        float s = 0.f;
#pragma unroll 8
        for (int j = 0; j < 64; j++) {
            float e = expf(Ss[tid][j] - m);
            Ss[tid][j] = e;
            s += e;
        }
        float inv = 1.f / s;
#pragma unroll 8
        for (int j = 0; j < 64; j += 2) {
            uint32_t hh, ll;
            split2(Ss[tid][j] * inv, Ss[tid][j + 1] * inv, hh, ll);
            const int w = j >> 1;
            const uint32_t off = (uint32_t)(tid * 128 +
                (((w >> 2) ^ (tid & 7)) * 16) + (w & 3) * 4);
            *(uint32_t*)(asm_ + 65536 + off) = hh;
            *(uint32_t*)(asm_ + 73728 + off) = ll;
        }
    }
    __syncthreads();

    uint32_t ph[4][4], pl[4][4];
    const uint32_t aPh = sb + 65536 + (uint32_t)((wid * 16 + la) * 128);
#pragma unroll
    for (int kt = 0; kt < 4; kt++) {
        LDSM_X4(ph[kt], aPh + coff[kt]);
        LDSM_X4(pl[kt], aPh + 8192 + coff[kt]);
    }
    const int tr0 = tok[wid * 16 + g];
    const int tr1 = tok[wid * 16 + g + 8];

    const __nv_bfloat16* sV[8];
    uint32_t dV[8];
#pragma unroll
    for (int i = 0; i < 8; i++) {
        const int id = tid + i * 128;
        const int p  = id >> 9;
        const int t  = (id >> 3) & 63;
        const int ci = id & 7;
        sV[i] = g_qkv2 + (size_t)tok[t] * 2304 + 1536 + p * 384 + ci * 8;
        dV[i] = sb + (uint32_t)(p * 8192 + t * 128 + ((ci ^ (t & 7)) * 16));
    }

#define PREF_V(co) do {                                                       \
        const uint32_t _o = ((co) & 1) * 32768u;                              \
        _Pragma("unroll")                                                     \
        for (int _i = 0; _i < 8; _i++) {                                      \
            asm volatile("cp.async.cg.shared.global [%0], [%1], 16;"          \
                :: "r"(dV[_i] + _o), "l"(sV[_i] + (co) * 64));                \
        }                                                                     \
        asm volatile("cp.async.commit_group;" ::: "memory");                  \
    } while (0)

    PREF_V(0);

    const uint32_t vbase = sb + (uint32_t)(((((lane >> 3) & 1) * 8) + (lane & 7)) * 128);

#pragma unroll
    for (int co = 0; co < 6; co++) {
        asm volatile("cp.async.wait_group 0;" ::: "memory");
        __syncthreads();
        if (co < 5) PREF_V(co + 1);
        const uint32_t st = (co & 1) * 32768u;
        const uint32_t bVh = vbase + st;
        const uint32_t bVl = bVh + 8192;

        float accO[8][4];
#pragma unroll
        for (int nt = 0; nt < 8; nt++)
#pragma unroll
            for (int i = 0; i < 4; i++) accO[nt][i] = 0.f;

#pragma unroll
        for (int kt = 0; kt < 4; kt++) {
#pragma unroll
            for (int ntp = 0; ntp < 4; ntp++) {
                uint32_t vh[4], vl[4];
                LDSM_X4_T(vh, bVh + kt * 2048 + coff[ntp]);
                LDSM_X4_T(vl, bVl + kt * 2048 + coff[ntp]);
                mma16816(accO[ntp * 2],     ph[kt], vh[0], vh[1]);
                mma16816(accO[ntp * 2 + 1], ph[kt], vh[2], vh[3]);
                mma16816(accO[ntp * 2],     pl[kt], vh[0], vh[1]);
                mma16816(accO[ntp * 2 + 1], pl[kt], vh[2], vh[3]);
                mma16816(accO[ntp * 2],     ph[kt], vl[0], vl[1]);
                mma16816(accO[ntp * 2 + 1], ph[kt], vl[2], vl[3]);
            }
        }
#pragma unroll
        for (int nt = 0; nt < 8; nt++) {
            const int col = co * 64 + nt * 8 + t4 * 2;
            __half2 h0 = __floats2half2_rn(accO[nt][0], accO[nt][1]);
            __half2 h1 = __floats2half2_rn(accO[nt][2], accO[nt][3]);
            *(__half2*)(g_att_h + (size_t)tr0 * CDIM + col) = h0;
            *(__half2*)(g_att_h + (size_t)tr1 * CDIM + col) = h1;
        }
    }
#undef PREF_V
}

// ---------------------------------------------------------------------------
extern "C" void kernel_launch(void* const* d_in, const int* in_sizes, int n_in,
                              void* d_out, int out_size)
{
    const float* x      = (const float*)d_in[0];
    const float* w_qkv  = (const float*)d_in[1];
    const float* b_qkv  = (const float*)d_in[2];
    const float* w_proj = (const float*)d_in[3];
    const float* b_proj = (const float*)d_in[4];
    float* out = (float*)d_out;

    __nv_bfloat16* qkv2 = nullptr;
    __half *atth = nullptr, *xh = nullptr, *wt1 = nullptr, *wt3 = nullptr;
    cudaGetSymbolAddress((void**)&qkv2, g_qkv2);
    cudaGetSymbolAddress((void**)&atth, g_att_h);
    cudaGetSymbolAddress((void**)&xh,   g_xh);
    cudaGetSymbolAddress((void**)&wt1,  g_Wt1);
    cudaGetSymbolAddress((void**)&wt3,  g_Wt3);

    cudaFuncSetAttribute(gemm_h, cudaFuncAttributeMaxDynamicSharedMemorySize,
                         3 * STAGE_BYTES);
    cudaFuncSetAttribute(window_attn, cudaFuncAttributeMaxDynamicSharedMemorySize,
                         ATTN_SMEM);

    // Weight transposes + x conversion (cheap)
    trans_w_kernel<<<(NQKV * CDIM + 255) / 256, 256>>>(w_qkv, wt1, NQKV);
    trans_w_kernel<<<(CDIM * CDIM + 255) / 256, 256>>>(w_proj, wt3, CDIM);
    cvt_h_kernel<<<TOKENS * 96 / 256, 256>>>(x, xh);

    // K1: qkv = x @ w_qkv + b_qkv  -> split-bf16 planes (g_qkv2)
    gemm_h<<<dim3(NQKV / 128, TOKENS / 128), 256, 3 * STAGE_BYTES>>>(
        xh, wt1, b_qkv, nullptr, qkv2, NQKV);

    // K2: per-window attention (tensor S and PV) -> fp16 g_att_h
    window_attn<<<NWIN, 128, ATTN_SMEM>>>();

    // K3: out = att @ w_proj + b_proj (fp32 out)
    gemm_h<<<dim3(CDIM / 128, TOKENS / 128), 256, 3 * STAGE_BYTES>>>(
        atth, wt3, b_proj, out, nullptr, CDIM);
}